// round 7
// baseline (speedup 1.0000x reference)
#include <cuda_runtime.h>
#include <cuda_bf16.h>
#include <math.h>
#include <stdint.h>

// ---------------- problem constants ----------------
#define FNUM  16
#define CCH   320
#define HWN   1024
#define BFN   32            // B*F
#define MTOK  32768         // BFN*HWN
#define NHEAD 8
#define DHEAD 40
#define NGRP  32
#define CPG   10
#define INNER 1280
#define NCTA  296           // 148 SMs * 2 CTAs

// ---------------- scratch ----------------
__device__ float g_hs [(size_t)MTOK * CCH];
__device__ float g_q  [(size_t)MTOK * CCH];
__device__ float g_k  [(size_t)MTOK * CCH];
__device__ float g_v  [(size_t)MTOK * CCH];
__device__ __nv_bfloat16 g_tokh[(size_t)MTOK * CCH];
__device__ __nv_bfloat16 g_tokl[(size_t)MTOK * CCH];
__device__ __nv_bfloat16 g_oh [(size_t)MTOK * CCH];
__device__ __nv_bfloat16 g_ol [(size_t)MTOK * CCH];
__device__ __nv_bfloat16 g_gh [(size_t)MTOK * INNER];
__device__ __nv_bfloat16 g_gl [(size_t)MTOK * INNER];
#define WTOT 2252800
__device__ __nv_bfloat16 g_wh[WTOT];
__device__ __nv_bfloat16 g_wl[WTOT];
__device__ float g_pe [FNUM * CCH];
__device__ float g_gnm[BFN * NGRP];
__device__ float g_gnr[BFN * NGRP];

// weight pool offsets (elements)
#define W_PIN   0
#define W_QKV0  102400
#define W_O0    409600
#define W_QKV1  512000
#define W_O1    819200
#define W_FF1   921600
#define W_FF2   1740800
#define W_POUT  2150400

// ================= helpers =================
__device__ __forceinline__ void ldsm4(uint32_t* r, const void* p) {
    uint32_t a = (uint32_t)__cvta_generic_to_shared(p);
    asm volatile("ldmatrix.sync.aligned.m8n8.x4.shared.b16 {%0,%1,%2,%3}, [%4];"
        : "=r"(r[0]), "=r"(r[1]), "=r"(r[2]), "=r"(r[3]) : "r"(a));
}
__device__ __forceinline__ void ldsm4t(uint32_t* r, const void* p) {
    uint32_t a = (uint32_t)__cvta_generic_to_shared(p);
    asm volatile("ldmatrix.sync.aligned.m8n8.x4.trans.shared.b16 {%0,%1,%2,%3}, [%4];"
        : "=r"(r[0]), "=r"(r[1]), "=r"(r[2]), "=r"(r[3]) : "r"(a));
}
__device__ __forceinline__ void mma16816(float* d, const uint32_t* a, const uint32_t* b) {
    asm volatile("mma.sync.aligned.m16n8k16.row.col.f32.bf16.bf16.f32 "
        "{%0,%1,%2,%3}, {%4,%5,%6,%7}, {%8,%9}, {%0,%1,%2,%3};"
        : "+f"(d[0]), "+f"(d[1]), "+f"(d[2]), "+f"(d[3])
        : "r"(a[0]), "r"(a[1]), "r"(a[2]), "r"(a[3]), "r"(b[0]), "r"(b[1]));
}
__device__ __forceinline__ void cpa16(void* dst, const void* src) {
    uint32_t d = (uint32_t)__cvta_generic_to_shared(dst);
    asm volatile("cp.async.cg.shared.global [%0], [%1], 16;" :: "r"(d), "l"(src));
}
#define CP_COMMIT() asm volatile("cp.async.commit_group;" ::: "memory")
#define CP_WAIT2()  asm volatile("cp.async.wait_group 2;" ::: "memory")

// ================= persistent bf16 hi/lo GEMM, 4-stage continuous pipeline ==
// MODE 0: C = v (+bias)
// MODE 1: C[perm(m),n] += v (+bias)
// MODE 2: out[(bf*CCH+n)*HWN+hw] = v + bias + X
// MODE 3: t = C[m,n]+v+bias; (Oh,Ol)[m,n] = split(t)
// MODE 4: QKV n-split into C/C2/C3
// MODE 5: FF1+GEGLU fused (interleaved weights): (Oh,Ol)[m,acol] = split(a*gelu(g))
#define SM_A_STG 10240            // 128 rows * 80B (APAD 40 bf16)
#define SM_B_STG 4096             // 32 rows * 128B, XOR-swizzled
#define SM_AH(s) ((s) * SM_A_STG)
#define SM_AL(s) (40960 + (s) * SM_A_STG)
#define SM_BH(s) (81920 + (s) * SM_B_STG)
#define SM_BL(s) (98304 + (s) * SM_B_STG)
#define SM_TOTAL 114688

// logical (row k, col n[elems, mult of 8]) -> swizzled byte offset in B stage
__device__ __forceinline__ uint32_t bswz(int k, int n) {
    uint32_t ch = (uint32_t)(n >> 3);
    return (uint32_t)(k * 128) + (((ch ^ (uint32_t)(k & 7)) << 4));
}

template <int MODE>
__global__ __launch_bounds__(256, 2) void bgemm_kernel(
    const __nv_bfloat16* __restrict__ Agh, const __nv_bfloat16* __restrict__ Agl,
    const __nv_bfloat16* __restrict__ Bgh, const __nv_bfloat16* __restrict__ Bgl,
    const float* __restrict__ bias, float* __restrict__ C,
    const float* __restrict__ X, float* __restrict__ C2, float* __restrict__ C3,
    __nv_bfloat16* __restrict__ Oh, __nv_bfloat16* __restrict__ Ol,
    int M, int N, int K)
{
    extern __shared__ char sm[];
    const int tid  = threadIdx.x;
    const int lane = tid & 31;
    const int wm   = (tid >> 5) & 3;
    const int wn   = tid >> 7;

    const int mbase = wm * 32;
    const int nbase = wn * 32;
    const int lrow  = lane & 15;
    const int lcol8 = (lane >> 4) * 8;

    const int ntx = N >> 6;            // tiles in N
    const int ntt = (M >> 7) * ntx;    // total tiles
    const int nkt = K >> 5;            // k-chunks per tile
    const int ncta = gridDim.x;

    const int arow0 = tid >> 1;
    const int ac0   = (tid & 1) * 2;
    const int brow  = tid >> 3;
    const int bch   = tid & 7;
    const uint32_t bstore = (uint32_t)(brow * 128) + (((uint32_t)(bch ^ (brow & 7))) << 4);

    auto load_chunk = [&](int c) {
        int tl = blockIdx.x + (c / nkt) * ncta;
        if (tl < ntt) {
            const int kt = (c % nkt) << 5;
            const int m0 = (tl / ntx) << 7;
            const int n0 = (tl % ntx) << 6;
            const int s  = c & 3;
            #pragma unroll
            for (int i = 0; i < 2; i++) {
                int ch = ac0 + i;
                size_t go = (size_t)(m0 + arow0) * K + kt + ch * 8;
                cpa16(sm + SM_AH(s) + arow0 * 80 + ch * 16, Agh + go);
                cpa16(sm + SM_AL(s) + arow0 * 80 + ch * 16, Agl + go);
            }
            size_t gb = (size_t)(kt + brow) * N + n0 + bch * 8;
            cpa16(sm + SM_BH(s) + bstore, Bgh + gb);
            cpa16(sm + SM_BL(s) + bstore, Bgl + gb);
        }
    };

    load_chunk(0); CP_COMMIT();
    load_chunk(1); CP_COMMIT();
    load_chunk(2); CP_COMMIT();

    float acc[2][4][4];
    #pragma unroll
    for (int a = 0; a < 2; a++)
        #pragma unroll
        for (int b = 0; b < 4; b++)
            #pragma unroll
            for (int c = 0; c < 4; c++) acc[a][b][c] = 0.f;

    int cc = 0;
    for (int tl = blockIdx.x; tl < ntt; tl += ncta) {
        for (int ktb = 0; ktb < nkt; ktb++, cc++) {
            CP_WAIT2();
            __syncthreads();
            load_chunk(cc + 3);
            CP_COMMIT();

            const int s = cc & 3;
            const char* pAH = sm + SM_AH(s);
            const char* pAL = sm + SM_AL(s);
            const char* pBH = sm + SM_BH(s);
            const char* pBL = sm + SM_BL(s);

            #pragma unroll
            for (int ks = 0; ks < 2; ks++) {
                uint32_t ah[2][4], al[2][4], bh[4][2], bl[4][2];
                #pragma unroll
                for (int mi = 0; mi < 2; mi++) {
                    int row = mbase + mi * 16 + lrow;
                    int cb  = (ks * 16 + lcol8) * 2;
                    ldsm4(ah[mi], pAH + row * 80 + cb);
                    ldsm4(al[mi], pAL + row * 80 + cb);
                }
                #pragma unroll
                for (int nj = 0; nj < 2; nj++) {
                    uint32_t off = bswz(ks * 16 + lrow, nbase + nj * 16 + lcol8);
                    uint32_t tmp[4];
                    ldsm4t(tmp, pBH + off);
                    bh[nj * 2][0] = tmp[0]; bh[nj * 2][1] = tmp[1];
                    bh[nj * 2 + 1][0] = tmp[2]; bh[nj * 2 + 1][1] = tmp[3];
                    ldsm4t(tmp, pBL + off);
                    bl[nj * 2][0] = tmp[0]; bl[nj * 2][1] = tmp[1];
                    bl[nj * 2 + 1][0] = tmp[2]; bl[nj * 2 + 1][1] = tmp[3];
                }
                #pragma unroll
                for (int mi = 0; mi < 2; mi++)
                    #pragma unroll
                    for (int ni = 0; ni < 4; ni++) {
                        mma16816(acc[mi][ni], ah[mi], bh[ni]);
                        mma16816(acc[mi][ni], ah[mi], bl[ni]);
                        mma16816(acc[mi][ni], al[mi], bh[ni]);
                    }
            }
        }

        // ---- epilogue for tile tl (overlaps next tile's in-flight loads) ----
        {
            const int m0 = (tl / ntx) << 7;
            const int n0 = (tl % ntx) << 6;
            const int erow = lane >> 2;
            const int ecol = (lane & 3) * 2;
            const int seg4 = (n0 + nbase) / CCH;   // MODE 4: constant per warp
            #pragma unroll
            for (int mi = 0; mi < 2; mi++) {
                #pragma unroll
                for (int rr = 0; rr < 2; rr++) {
                    const int m = m0 + mbase + mi * 16 + rr * 8 + erow;
                    if (MODE == 5) {
                        #pragma unroll
                        for (int p = 0; p < 2; p++) {
                            const int tile16 = (n0 + nbase + p * 16) >> 4;
                            const int acol = tile16 * 8 + ecol;
                            float a0 = acc[mi][2 * p][rr * 2 + 0] + bias[acol];
                            float a1 = acc[mi][2 * p][rr * 2 + 1] + bias[acol + 1];
                            float g0 = acc[mi][2 * p + 1][rr * 2 + 0] + bias[INNER + acol];
                            float g1 = acc[mi][2 * p + 1][rr * 2 + 1] + bias[INNER + acol + 1];
                            float r0 = a0 * (0.5f * g0 * (1.f + erff(g0 * 0.7071067811865476f)));
                            float r1 = a1 * (0.5f * g1 * (1.f + erff(g1 * 0.7071067811865476f)));
                            __nv_bfloat16 h0 = __float2bfloat16_rn(r0);
                            __nv_bfloat16 h1 = __float2bfloat16_rn(r1);
                            uint32_t hp = (uint32_t)__bfloat16_as_ushort(h0) | ((uint32_t)__bfloat16_as_ushort(h1) << 16);
                            uint32_t lp = (uint32_t)__bfloat16_as_ushort(__float2bfloat16_rn(r0 - __bfloat162float(h0)))
                                        | ((uint32_t)__bfloat16_as_ushort(__float2bfloat16_rn(r1 - __bfloat162float(h1))) << 16);
                            size_t off = (size_t)m * INNER + acol;
                            *(uint32_t*)(Oh + off) = hp;
                            *(uint32_t*)(Ol + off) = lp;
                        }
                    } else {
                        int mrow = m;
                        if (MODE == 1) {
                            int f = m & 15, nd = m >> 4;
                            mrow = (((nd >> 10) * FNUM + f) << 10) + (nd & 1023);
                        }
                        const int bfi = m >> 10, hw = m & 1023;
                        #pragma unroll
                        for (int ni = 0; ni < 4; ni++) {
                            const int n = n0 + nbase + ni * 8 + ecol;
                            float v0 = acc[mi][ni][rr * 2 + 0];
                            float v1 = acc[mi][ni][rr * 2 + 1];
                            if (bias) { v0 += bias[n]; v1 += bias[n + 1]; }
                            if (MODE == 0) {
                                *(float2*)(C + (size_t)mrow * N + n) = make_float2(v0, v1);
                            } else if (MODE == 1) {
                                float2* p = (float2*)(C + (size_t)mrow * N + n);
                                float2 old = *p;
                                old.x += v0; old.y += v1;
                                *p = old;
                            } else if (MODE == 2) {
                                size_t off = ((size_t)(bfi * CCH + n)) * HWN + hw;
                                C[off] = v0 + X[off];
                                C[off + HWN] = v1 + X[off + HWN];
                            } else if (MODE == 3) {
                                size_t off = (size_t)mrow * N + n;
                                float t0 = C[off] + v0;
                                float t1 = C[off + 1] + v1;
                                __nv_bfloat16 h0 = __float2bfloat16_rn(t0);
                                __nv_bfloat16 h1 = __float2bfloat16_rn(t1);
                                uint32_t hp = (uint32_t)__bfloat16_as_ushort(h0) | ((uint32_t)__bfloat16_as_ushort(h1) << 16);
                                uint32_t lp = (uint32_t)__bfloat16_as_ushort(__float2bfloat16_rn(t0 - __bfloat162float(h0)))
                                            | ((uint32_t)__bfloat16_as_ushort(__float2bfloat16_rn(t1 - __bfloat162float(h1))) << 16);
                                *(uint32_t*)(Oh + off) = hp;
                                *(uint32_t*)(Ol + off) = lp;
                            } else { // MODE 4
                                float* dst = (seg4 == 0) ? C : (seg4 == 1) ? C2 : C3;
                                *(float2*)(dst + (size_t)m * CCH + (n - seg4 * CCH)) = make_float2(v0, v1);
                            }
                        }
                    }
                }
            }
        }
        #pragma unroll
        for (int a = 0; a < 2; a++)
            #pragma unroll
            for (int b = 0; b < 4; b++)
                #pragma unroll
                for (int c = 0; c < 4; c++) acc[a][b][c] = 0.f;
    }
}

// ---------------- batched weight fp32 -> bf16 hi/lo -------------------------
struct WSegs {
    const float* src[12];
    int off[12], rows[12], cols[12], pitch[12], coloff[12], ilv[12], blk0[12];
};
__global__ __launch_bounds__(256) void convw_all(WSegs T,
    __nv_bfloat16* __restrict__ dh, __nv_bfloat16* __restrict__ dl)
{
    int b = blockIdx.x;
    int s = 0;
    #pragma unroll
    for (int i = 1; i < 12; i++) if (b >= T.blk0[i]) s = i;
    int idx = (b - T.blk0[s]) * 256 + threadIdx.x;
    int cols = T.cols[s];
    if (idx >= T.rows[s] * cols) return;
    int r = idx / cols, c = idx % cols;
    float v = T.src[s][idx];
    int nc;
    if (T.ilv[s]) {
        int half = cols >> 1;
        if (c < half) nc = (c >> 3) * 16 + (c & 7);
        else { int c2 = c - half; nc = (c2 >> 3) * 16 + 8 + (c2 & 7); }
    } else {
        nc = T.coloff[s] + c;
    }
    size_t off = (size_t)T.off[s] + (size_t)r * T.pitch[s] + nc;
    __nv_bfloat16 h = __float2bfloat16_rn(v);
    dh[off] = h;
    dl[off] = __float2bfloat16_rn(v - __bfloat162float(h));
}

// ---------------- PE ----------------
__global__ void pe_kernel(float* __restrict__ pe)
{
    int p = blockIdx.x;
    int i = threadIdx.x;
    double div = exp((double)(2 * i) * (-log(10000.0) / (double)CCH));
    double a = (double)p * div;
    pe[p * CCH + 2 * i]     = (float)sin(a);
    pe[p * CCH + 2 * i + 1] = (float)cos(a);
}

// ---------------- GroupNorm stats ----------------
__global__ __launch_bounds__(256) void gn_stats_kernel(
    const float* __restrict__ x, float* __restrict__ mean, float* __restrict__ rstd)
{
    int bg = blockIdx.x;
    int bf = bg >> 5, g = bg & 31;
    const float* p = x + ((size_t)bf * CCH + g * CPG) * HWN;
    float s = 0.f, q = 0.f;
    for (int idx = threadIdx.x; idx < CPG * HWN; idx += 256) {
        float v = p[idx];
        s += v; q += v * v;
    }
    #pragma unroll
    for (int o = 16; o > 0; o >>= 1) {
        s += __shfl_xor_sync(0xffffffffu, s, o);
        q += __shfl_xor_sync(0xffffffffu, q, o);
    }
    __shared__ float ss[8], qq[8];
    int warp = threadIdx.x >> 5, lane = threadIdx.x & 31;
    if (lane == 0) { ss[warp] = s; qq[warp] = q; }
    __syncthreads();
    if (threadIdx.x == 0) {
        float S = 0.f, Q = 0.f;
        #pragma unroll
        for (int i = 0; i < 8; i++) { S += ss[i]; Q += qq[i]; }
        float m = S / (float)(CPG * HWN);
        float var = Q / (float)(CPG * HWN) - m * m;
        mean[bg] = m;
        rstd[bg] = rsqrtf(var + 1e-6f);
    }
}

// ---------------- GroupNorm apply + transpose -> bf16 hi/lo ----------------
__global__ void gn_tok_kernel(
    const float* __restrict__ x, const float* __restrict__ gw, const float* __restrict__ gb,
    const float* __restrict__ mean, const float* __restrict__ rstd,
    __nv_bfloat16* __restrict__ th, __nv_bfloat16* __restrict__ tl)
{
    __shared__ float tile[32][33];
    int bf = blockIdx.z;
    int c0 = blockIdx.y * 32;
    int hw0 = blockIdx.x * 32;
    #pragma unroll
    for (int j = 0; j < 4; j++) {
        int c = c0 + threadIdx.y + j * 8;
        float v = x[((size_t)bf * CCH + c) * HWN + hw0 + threadIdx.x];
        int bg = bf * NGRP + c / CPG;
        v = (v - mean[bg]) * rstd[bg] * gw[c] + gb[c];
        tile[threadIdx.y + j * 8][threadIdx.x] = v;
    }
    __syncthreads();
    #pragma unroll
    for (int j = 0; j < 4; j++) {
        int hw = hw0 + threadIdx.y + j * 8;
        float v = tile[threadIdx.x][threadIdx.y + j * 8];
        __nv_bfloat16 h = __float2bfloat16_rn(v);
        size_t off = ((size_t)bf * HWN + hw) * CCH + c0 + threadIdx.x;
        th[off] = h;
        tl[off] = __float2bfloat16_rn(v - __bfloat162float(h));
    }
}

// ---------------- LayerNorm -> bf16 hi/lo ----------------
__global__ __launch_bounds__(320) void ln_kernel(
    const float* __restrict__ in, const float* __restrict__ w, const float* __restrict__ bvec,
    const float* __restrict__ pe,
    __nv_bfloat16* __restrict__ oh, __nv_bfloat16* __restrict__ ol, int temporal)
{
    int r = blockIdx.x;
    int c = threadIdx.x;
    int src = r, f = 0;
    if (temporal) {
        f = r & 15;
        int nd = r >> 4;
        src = (((nd >> 10) * FNUM + f) << 10) + (nd & 1023);
    }
    float v = in[(size_t)src * CCH + c];
    float s = v, q = v * v;
    #pragma unroll
    for (int o = 16; o > 0; o >>= 1) {
        s += __shfl_xor_sync(0xffffffffu, s, o);
        q += __shfl_xor_sync(0xffffffffu, q, o);
    }
    __shared__ float ss[10], qq[10];
    __shared__ float mb[2];
    int warp = c >> 5, lane = c & 31;
    if (lane == 0) { ss[warp] = s; qq[warp] = q; }
    __syncthreads();
    if (c == 0) {
        float S = 0.f, Q = 0.f;
        #pragma unroll
        for (int i = 0; i < 10; i++) { S += ss[i]; Q += qq[i]; }
        float m = S / (float)CCH;
        float var = Q / (float)CCH - m * m;
        mb[0] = m; mb[1] = rsqrtf(var + 1e-5f);
    }
    __syncthreads();
    float o2 = (v - mb[0]) * mb[1] * w[c] + bvec[c];
    if (temporal) o2 += pe[f * CCH + c];
    __nv_bfloat16 h = __float2bfloat16_rn(o2);
    oh[(size_t)r * CCH + c] = h;
    ol[(size_t)r * CCH + c] = __float2bfloat16_rn(o2 - __bfloat162float(h));
}

// ---------------- temporal attention (block per token-group n) -------------
#define ATT_PITCH 321
#define ATT_SMEM ((3 * 16 * ATT_PITCH + 8 * 16 * 16) * 4)
__global__ __launch_bounds__(256) void attn_kernel(
    const float* __restrict__ Q, const float* __restrict__ K,
    const float* __restrict__ V,
    __nv_bfloat16* __restrict__ Oh, __nv_bfloat16* __restrict__ Ol)
{
    extern __shared__ float smf[];
    float* qs = smf;
    float* ks = smf + 16 * ATT_PITCH;
    float* vs = smf + 2 * 16 * ATT_PITCH;
    float* sc = smf + 3 * 16 * ATT_PITCH;   // [8][16][16]
    const int tid = threadIdx.x;
    const size_t base = (size_t)blockIdx.x * FNUM * CCH;

    #pragma unroll
    for (int i = 0; i < 5; i++) {
        int idx4 = tid + i * 256;
        int row = idx4 / 80;
        int c4 = (idx4 % 80) * 4;
        float4 a = *(const float4*)(Q + base + row * CCH + c4);
        qs[row * ATT_PITCH + c4] = a.x; qs[row * ATT_PITCH + c4 + 1] = a.y;
        qs[row * ATT_PITCH + c4 + 2] = a.z; qs[row * ATT_PITCH + c4 + 3] = a.w;
        float4 b = *(const float4*)(K + base + row * CCH + c4);
        ks[row * ATT_PITCH + c4] = b.x; ks[row * ATT_PITCH + c4 + 1] = b.y;
        ks[row * ATT_PITCH + c4 + 2] = b.z; ks[row * ATT_PITCH + c4 + 3] = b.w;
        float4 cc = *(const float4*)(V + base + row * CCH + c4);
        vs[row * ATT_PITCH + c4] = cc.x; vs[row * ATT_PITCH + c4 + 1] = cc.y;
        vs[row * ATT_PITCH + c4 + 2] = cc.z; vs[row * ATT_PITCH + c4 + 3] = cc.w;
    }
    __syncthreads();

    {
        const int qf = tid >> 4, kf = tid & 15;
        const float* qp = qs + qf * ATT_PITCH;
        const float* kp = ks + kf * ATT_PITCH;
        #pragma unroll
        for (int h = 0; h < 8; h++) {
            float s = 0.f;
            #pragma unroll
            for (int j = 0; j < DHEAD; j++) s = fmaf(qp[h * DHEAD + j], kp[h * DHEAD + j], s);
            sc[h * 256 + qf * 16 + kf] = s * 0.15811388300841897f;
        }
    }
    __syncthreads();

    if (tid < 128) {
        float* row = sc + (tid >> 4) * 256 + (tid & 15) * 16;
        float m = -1e30f;
        #pragma unroll
        for (int k2 = 0; k2 < 16; k2++) m = fmaxf(m, row[k2]);
        float sum = 0.f;
        #pragma unroll
        for (int k2 = 0; k2 < 16; k2++) {
            float e = expf(row[k2] - m);
            row[k2] = e;
            sum += e;
        }
        float inv = 1.f / sum;
        #pragma unroll
        for (int k2 = 0; k2 < 16; k2++) row[k2] *= inv;
    }
    __syncthreads();

    #pragma unroll
    for (int i = 0; i < 20; i++) {
        int idx = tid + i * 256;
        int f = idx / CCH, c = idx % CCH;
        int h = c / DHEAD;
        const float* pr = sc + h * 256 + f * 16;
        float o = 0.f;
        #pragma unroll
        for (int k2 = 0; k2 < 16; k2++) o = fmaf(pr[k2], vs[k2 * ATT_PITCH + c], o);
        size_t gi = base + (size_t)f * CCH + c;
        __nv_bfloat16 hh = __float2bfloat16_rn(o);
        Oh[gi] = hh;
        Ol[gi] = __float2bfloat16_rn(o - __bfloat162float(hh));
    }
}

// ---------------- host orchestration ----------------
extern "C" void kernel_launch(void* const* d_in, const int* in_sizes, int n_in,
                              void* d_out, int out_size)
{
    const float* x      = (const float*)d_in[0];
    const float* gn_w   = (const float*)d_in[1];
    const float* gn_b   = (const float*)d_in[2];
    const float* pin_w  = (const float*)d_in[3];
    const float* pin_b  = (const float*)d_in[4];
    const float* lnw[2]  = { (const float*)d_in[5],  (const float*)d_in[12] };
    const float* lnb[2]  = { (const float*)d_in[6],  (const float*)d_in[13] };
    const float* wq[2]   = { (const float*)d_in[7],  (const float*)d_in[14] };
    const float* wk[2]   = { (const float*)d_in[8],  (const float*)d_in[15] };
    const float* wv[2]   = { (const float*)d_in[9],  (const float*)d_in[16] };
    const float* wo[2]   = { (const float*)d_in[10], (const float*)d_in[17] };
    const float* bo[2]   = { (const float*)d_in[11], (const float*)d_in[18] };
    const float* ffln_w = (const float*)d_in[19];
    const float* ffln_b = (const float*)d_in[20];
    const float* ff_w1  = (const float*)d_in[21];
    const float* ff_b1  = (const float*)d_in[22];
    const float* ff_w2  = (const float*)d_in[23];
    const float* ff_b2  = (const float*)d_in[24];
    const float* pout_w = (const float*)d_in[25];
    const float* pout_b = (const float*)d_in[26];
    float* out = (float*)d_out;

    float *hs, *q, *k, *v, *pe, *gnm, *gnr;
    __nv_bfloat16 *tokh, *tokl, *oh, *ol, *gh, *gl, *wh, *wl;
    cudaGetSymbolAddress((void**)&hs,  g_hs);
    cudaGetSymbolAddress((void**)&q,   g_q);
    cudaGetSymbolAddress((void**)&k,   g_k);
    cudaGetSymbolAddress((void**)&v,   g_v);
    cudaGetSymbolAddress((void**)&pe,  g_pe);
    cudaGetSymbolAddress((void**)&gnm, g_gnm);
    cudaGetSymbolAddress((void**)&gnr, g_gnr);
    cudaGetSymbolAddress((void**)&tokh, g_tokh);
    cudaGetSymbolAddress((void**)&tokl, g_tokl);
    cudaGetSymbolAddress((void**)&oh,  g_oh);
    cudaGetSymbolAddress((void**)&ol,  g_ol);
    cudaGetSymbolAddress((void**)&gh,  g_gh);
    cudaGetSymbolAddress((void**)&gl,  g_gl);
    cudaGetSymbolAddress((void**)&wh,  g_wh);
    cudaGetSymbolAddress((void**)&wl,  g_wl);

    cudaFuncSetAttribute(bgemm_kernel<0>, cudaFuncAttributeMaxDynamicSharedMemorySize, SM_TOTAL);
    cudaFuncSetAttribute(bgemm_kernel<1>, cudaFuncAttributeMaxDynamicSharedMemorySize, SM_TOTAL);
    cudaFuncSetAttribute(bgemm_kernel<2>, cudaFuncAttributeMaxDynamicSharedMemorySize, SM_TOTAL);
    cudaFuncSetAttribute(bgemm_kernel<3>, cudaFuncAttributeMaxDynamicSharedMemorySize, SM_TOTAL);
    cudaFuncSetAttribute(bgemm_kernel<4>, cudaFuncAttributeMaxDynamicSharedMemorySize, SM_TOTAL);
    cudaFuncSetAttribute(bgemm_kernel<5>, cudaFuncAttributeMaxDynamicSharedMemorySize, SM_TOTAL);
    cudaFuncSetAttribute(attn_kernel, cudaFuncAttributeMaxDynamicSharedMemorySize, ATT_SMEM);

    pe_kernel<<<FNUM, CCH / 2>>>(pe);
    gn_stats_kernel<<<BFN * NGRP, 256>>>(x, gnm, gnr);
    gn_tok_kernel<<<dim3(HWN / 32, CCH / 32, BFN), dim3(32, 8)>>>(x, gn_w, gn_b, gnm, gnr, tokh, tokl);

    // single batched weight conversion
    {
        WSegs T;
        const float* srcs[12] = { pin_w, wq[0], wk[0], wv[0], wo[0],
                                  wq[1], wk[1], wv[1], wo[1], ff_w1, ff_w2, pout_w };
        int offs[12]  = { W_PIN, W_QKV0, W_QKV0, W_QKV0, W_O0,
                          W_QKV1, W_QKV1, W_QKV1, W_O1, W_FF1, W_FF2, W_POUT };
        int rows[12]  = { 320, 320, 320, 320, 320, 320, 320, 320, 320, 320, 1280, 320 };
        int cols[12]  = { 320, 320, 320, 320, 320, 320, 320, 320, 320, 2560, 320, 320 };
        int pitch[12] = { 320, 960, 960, 960, 320, 960, 960, 960, 320, 2560, 320, 320 };
        int colo[12]  = { 0, 0, 320, 640, 0, 0, 320, 640, 0, 0, 0, 0 };
        int ilv[12]   = { 0, 0, 0, 0, 0, 0, 0, 0, 0, 1, 0, 0 };
        int blk = 0;
        for (int i = 0; i < 12; i++) {
            T.src[i] = srcs[i]; T.off[i] = offs[i]; T.rows[i] = rows[i]; T.cols[i] = cols[i];
            T.pitch[i] = pitch[i]; T.coloff[i] = colo[i]; T.ilv[i] = ilv[i];
            T.blk0[i] = blk;
            blk += (rows[i] * cols[i] + 255) / 256;
        }
        convw_all<<<blk, 256>>>(T, wh, wl);
    }

    // proj_in
    bgemm_kernel<0><<<NCTA, 256, SM_TOTAL>>>(tokh, tokl, wh + W_PIN, wl + W_PIN,
        pin_b, hs, nullptr, nullptr, nullptr, nullptr, nullptr, MTOK, CCH, CCH);

    const int WQKV[2] = { W_QKV0, W_QKV1 };
    const int WO[2]   = { W_O0, W_O1 };
    for (int i = 0; i < 2; i++) {
        ln_kernel<<<MTOK, CCH>>>(hs, lnw[i], lnb[i], pe, tokh, tokl, 1);
        bgemm_kernel<4><<<NCTA, 256, SM_TOTAL>>>(tokh, tokl, wh + WQKV[i], wl + WQKV[i],
            nullptr, q, nullptr, k, v, nullptr, nullptr, MTOK, 960, CCH);
        attn_kernel<<<2048, 256, ATT_SMEM>>>(q, k, v, oh, ol);
        bgemm_kernel<1><<<NCTA, 256, SM_TOTAL>>>(oh, ol, wh + WO[i], wl + WO[i],
            bo[i], hs, nullptr, nullptr, nullptr, nullptr, nullptr, MTOK, CCH, CCH);
    }

    ln_kernel<<<MTOK, CCH>>>(hs, ffln_w, ffln_b, pe, tokh, tokl, 0);
    // FF1 + GEGLU fused (interleaved weights) -> gh/gl
    bgemm_kernel<5><<<NCTA, 256, SM_TOTAL>>>(tokh, tokl, wh + W_FF1, wl + W_FF1,
        ff_b1, nullptr, nullptr, nullptr, nullptr, gh, gl, MTOK, 2 * INNER, CCH);
    // FF down-proj + residual -> bf16 hi/lo (into tokh/tokl)
    bgemm_kernel<3><<<NCTA, 256, SM_TOTAL>>>(gh, gl, wh + W_FF2, wl + W_FF2,
        ff_b2, hs, nullptr, nullptr, nullptr, tokh, tokl, MTOK, CCH, INNER);
    // proj_out + spatial residual
    bgemm_kernel<2><<<NCTA, 256, SM_TOTAL>>>(tokh, tokl, wh + W_POUT, wl + W_POUT,
        pout_b, out, x, nullptr, nullptr, nullptr, nullptr, MTOK, CCH, CCH);
}